// round 16
// baseline (speedup 1.0000x reference)
#include <cuda_runtime.h>
#include <cuda_fp16.h>
#include <cstdint>
#include <math.h>

// Problem constants
#define BB 4
#define TT 2048
#define DD 1024
#define HH 16
#define DH 64
#define MTOT (BB*TT)        // 8192
#define N_QKV (3*DD)        // 3072
#define N_KV  (2*DD)        // 2048

// Scratch (device globals: allocation-guard safe). ALL single fp16.
__device__ __half g_wqkv[(size_t)N_QKV * DD];    // W_qkv^T [3072,1024]
__device__ __half g_wout[(size_t)DD * DD];       // W_out^T
__device__ __half g_act[(size_t)MTOT * DD];      // activations [M,K]
#define QKV_ELEMS ((size_t)BB * HH * TT * DH)
__device__ __half g_q[QKV_ELEMS];                // Q (pre-scaled 1/8)
__device__ __half g_k[QKV_ELEMS];                // K (compacted)
__device__ __half g_v[QKV_ELEMS];                // V (compacted)
// mask compaction: counts and compacted-index -> token map
__device__ int g_toklist[BB * TT];
__device__ int g_ncomp[BB];

// ---------------------------------------------------------------------------
// sm_80-portable PTX helpers
// ---------------------------------------------------------------------------
__device__ __forceinline__ uint32_t smem_u32(const void* p) {
    uint32_t a;
    asm("{ .reg .u64 t; cvta.to.shared.u64 t, %1; cvt.u32.u64 %0, t; }"
        : "=r"(a) : "l"(p));
    return a;
}
__device__ __forceinline__ void cpa16(uint32_t dst, const void* src) {
    asm volatile("cp.async.cg.shared.global [%0], [%1], 16;"
                 :: "r"(dst), "l"(src));
}
#define CP_COMMIT() asm volatile("cp.async.commit_group;" ::: "memory")
#define CP_WAIT(n)  asm volatile("cp.async.wait_group %0;" :: "n"(n) : "memory")

__device__ __forceinline__ void ldsm4(uint32_t* r, uint32_t addr) {
    asm volatile("ldmatrix.sync.aligned.m8n8.x4.shared.b16 {%0,%1,%2,%3}, [%4];"
                 : "=r"(r[0]), "=r"(r[1]), "=r"(r[2]), "=r"(r[3]) : "r"(addr));
}
__device__ __forceinline__ void ldsm4t(uint32_t* r, uint32_t addr) {
    asm volatile("ldmatrix.sync.aligned.m8n8.x4.trans.shared.b16 {%0,%1,%2,%3}, [%4];"
                 : "=r"(r[0]), "=r"(r[1]), "=r"(r[2]), "=r"(r[3]) : "r"(addr));
}
__device__ __forceinline__ void mma_f16(float* d, const uint32_t* a,
                                        const uint32_t* b) {
    asm volatile("mma.sync.aligned.m16n8k16.row.col.f32.f16.f16.f32 "
                 "{%0,%1,%2,%3}, {%4,%5,%6,%7}, {%8,%9}, {%0,%1,%2,%3};"
                 : "+f"(d[0]), "+f"(d[1]), "+f"(d[2]), "+f"(d[3])
                 : "r"(a[0]), "r"(a[1]), "r"(a[2]), "r"(a[3]),
                   "r"(b[0]), "r"(b[1]));
}
__device__ __forceinline__ uint32_t pack2h(float x, float y) {
    __half2 h;
    h.x = __float2half(x);
    h.y = __float2half(y);
    return *(uint32_t*)&h;
}

// ---------------------------------------------------------------------------
// Fused conversion kernel: weights + activations to fp16, mask scan.
// ---------------------------------------------------------------------------
__device__ __forceinline__ void conv_w_body(
    const float* __restrict__ W, __half* __restrict__ Wt,
    int K, int N, int bx, int by, int tid)
{
    __shared__ float t[32][33];
    const int n0 = bx * 32, k0 = by * 32;
    const int tx = tid & 31, ty = tid >> 5;
    #pragma unroll
    for (int i = 0; i < 32; i += 8)
        t[ty + i][tx] = W[(size_t)(k0 + ty + i) * N + n0 + tx];
    __syncthreads();
    #pragma unroll
    for (int i = 0; i < 32; i += 8) {
        int n = ty + i;
        Wt[(size_t)(n0 + n) * K + k0 + tx] = __float2half(t[tx][n]);
    }
}

__global__ __launch_bounds__(256)
void conv_all_kernel(const float* __restrict__ W_qkv,
                     const float* __restrict__ W_out,
                     const float* __restrict__ x,
                     const int* __restrict__ mask,
                     __half* __restrict__ wq, __half* __restrict__ wo,
                     __half* __restrict__ xs,
                     int* __restrict__ toklist, int* __restrict__ ncomp)
{
    const int bid = blockIdx.x, tid = threadIdx.x;
    if (bid < 3072) {
        conv_w_body(W_qkv, wq, DD, N_QKV, bid % 96, bid / 96, tid);
    } else if (bid < 4096) {
        const int id = bid - 3072;
        conv_w_body(W_out, wo, DD, DD, id % 32, id / 32, tid);
    } else if (bid < 8192) {
        const int base = (bid - 4096) * 512 + tid;
        #pragma unroll
        for (int u = 0; u < 2; u++) {
            int idx = base + u * 256;
            float4 v = ((const float4*)x)[idx];
            ((uint32_t*)xs)[idx * 2 + 0] = pack2h(v.x, v.y);
            ((uint32_t*)xs)[idx * 2 + 1] = pack2h(v.z, v.w);
        }
    } else {
        const int bb = bid - 8192;
        const int* mrow = mask + bb * TT;
        __shared__ int part[256];
        int loc[8];
        int s = 0;
        const int base = tid * 8;
        #pragma unroll
        for (int i = 0; i < 8; i++) {
            loc[i] = s;
            s += (mrow[base + i] != 0) ? 1 : 0;
        }
        part[tid] = s;
        __syncthreads();
        for (int off = 1; off < 256; off <<= 1) {
            int v = (tid >= off) ? part[tid - off] : 0;
            __syncthreads();
            part[tid] += v;
            __syncthreads();
        }
        const int excl = (tid == 0) ? 0 : part[tid - 1];
        #pragma unroll
        for (int i = 0; i < 8; i++)
            if (mrow[base + i] != 0)
                toklist[bb * TT + excl + loc[i]] = base + i;
        if (tid == 255) ncomp[bb] = part[255];
    }
}

// ---------------------------------------------------------------------------
// GEMM machinery: single fp16 A and B. BK=64, 2-stage, 144B rows
// (64 halves + 16B pad; bank walk 36r mod 32 -> conflict-free ldsm).
// ---------------------------------------------------------------------------
#define GBK 64
#define GROWB 144
#define MATB (128 * GROWB)             // 18432 bytes per matrix tile
#define ST_A  0
#define ST_B  MATB
#define STAGE_B (2 * MATB)             // 36864
#define GEMM_SMEM (2 * STAGE_B)        // 73728

__device__ __forceinline__ void gemm_compute_chunk(
    uint32_t st, int wm, int wn,
    int a_r, int a_k, int b_r, int b_k,
    float acc[4][4][4])
{
    #pragma unroll
    for (int ks = 0; ks < 4; ks++) {
        const int k0 = ks * 16;
        uint32_t bf[4][2];
        #pragma unroll
        for (int half = 0; half < 2; half++) {
            uint32_t baddr = (uint32_t)((wn * 32 + half * 16 + b_r) * GROWB
                                        + (k0 + b_k) * 2);
            uint32_t r[4];
            ldsm4(r, st + ST_B + baddr);
            bf[half * 2 + 0][0] = r[0]; bf[half * 2 + 0][1] = r[1];
            bf[half * 2 + 1][0] = r[2]; bf[half * 2 + 1][1] = r[3];
        }
        #pragma unroll
        for (int mi = 0; mi < 4; mi++) {
            uint32_t aaddr = (uint32_t)((wm * 64 + mi * 16 + a_r) * GROWB
                                        + (k0 + a_k) * 2);
            uint32_t a4[4];
            ldsm4(a4, st + ST_A + aaddr);
            #pragma unroll
            for (int nf = 0; nf < 4; nf++) mma_f16(acc[mi][nf], a4, bf[nf]);
        }
    }
}

__device__ __forceinline__ void gemm_load_chunk_rows(
    uint32_t stBase,
    const __half* __restrict__ A, const __half* __restrict__ B,
    size_t a_row_off, size_t b_row_off, int k0, int tid)
{
    // thread covers 64B (4x16B) of its row half; a/b_row_off include kc
    const int row = tid >> 1;
    const int kc  = (tid & 1) * 32;     // halves
    const uint32_t so = (uint32_t)(row * GROWB + kc * 2);
    #pragma unroll
    for (int u = 0; u < 4; u++) {
        cpa16(stBase + ST_A + so + u * 16, A + a_row_off + k0 + u * 8);
        cpa16(stBase + ST_B + so + u * 16, B + b_row_off + k0 + u * 8);
    }
}

__device__ __forceinline__ void gemm_core(
    uint32_t sb,
    const __half* __restrict__ A, const __half* __restrict__ B,
    size_t a_off, size_t b_off, int tid, int wm, int wn,
    int a_r, int a_k, int b_r, int b_k, float acc[4][4][4])
{
    const int NCH = DD / GBK;   // 16
    gemm_load_chunk_rows(sb, A, B, a_off, b_off, 0, tid);
    CP_COMMIT();
    for (int c = 0; c < NCH; c++) {
        const uint32_t st = sb + (uint32_t)(c & 1) * STAGE_B;
        if (c + 1 < NCH) {
            gemm_load_chunk_rows(sb + (uint32_t)((c + 1) & 1) * STAGE_B,
                                 A, B, a_off, b_off, (c + 1) * GBK, tid);
            CP_COMMIT();
            CP_WAIT(1);
        } else {
            CP_WAIT(0);
        }
        __syncthreads();
        gemm_compute_chunk(st, wm, wn, a_r, a_k, b_r, b_k, acc);
        __syncthreads();
    }
}

// ---------------------------------------------------------------------------
// Fused projection kernel: blocks [0,512) = Q (dense, scatter pre-scaled);
// blocks [512,1536) = K/V over compacted tokens only.
// ---------------------------------------------------------------------------
__global__ __launch_bounds__(256, 2)
void gemm_proj_kernel(const __half* __restrict__ A,
                      const __half* __restrict__ W,
                      const float* __restrict__ bias,
                      __half* q_g, __half* k_g, __half* v_g,
                      const int* __restrict__ toklist,
                      const int* __restrict__ ncomp)
{
    extern __shared__ char smraw[];
    const uint32_t sb = smem_u32(smraw);
    const int tid = threadIdx.x, wid = tid >> 5, lane = tid & 31;
    const int wm = wid >> 2, wn = wid & 3;
    const int a_r = (lane & 7) + ((lane >> 3) & 1) * 8;
    const int a_k = (lane >> 4) * 8;
    const int b_r = (lane & 7) + (lane >> 4) * 8;
    const int b_k = ((lane >> 3) & 1) * 8;
    const int row = tid >> 1, kc = (tid & 1) * 32;

    float acc[4][4][4];
    #pragma unroll
    for (int i = 0; i < 4; i++)
        #pragma unroll
        for (int j = 0; j < 4; j++)
            #pragma unroll
            for (int v = 0; v < 4; v++) acc[i][j][v] = 0.0f;

    if (blockIdx.x < 512) {
        // ---- Q path ----
        const int qid = blockIdx.x;
        const int bn0 = (qid & 7) * 128;
        const int bm0 = (qid >> 3) * 128;
        const size_t a_off = (size_t)(bm0 + row) * DD + kc;
        const size_t b_off = (size_t)(bn0 + row) * DD + kc;
        gemm_core(sb, A, W, a_off, b_off,
                  tid, wm, wn, a_r, a_k, b_r, b_k, acc);

        #pragma unroll
        for (int mi = 0; mi < 4; mi++) {
            const int orow = bm0 + wm * 64 + mi * 16 + (lane >> 2);
            #pragma unroll
            for (int nf = 0; nf < 4; nf++) {
                const int col = bn0 + wn * 32 + nf * 8 + (lane & 3) * 2;
                const float b0 = bias[col], b1 = bias[col + 1];
                float v0 = acc[mi][nf][0] + b0, v1 = acc[mi][nf][1] + b1;
                float v2 = acc[mi][nf][2] + b0, v3 = acc[mi][nf][3] + b1;
                const int hh  = (col >> 6) & 15;
                const int d   = col & 63;
                const int bb  = orow >> 11;
                const int trow = orow & 2047;
                size_t dst = (((size_t)(bb * 16 + hh)) * TT + trow) * 64 + d;
                *(uint32_t*)(q_g + dst) = pack2h(v0 * 0.125f, v1 * 0.125f);
                *(uint32_t*)(q_g + dst + 8 * 64) = pack2h(v2 * 0.125f, v3 * 0.125f);
            }
        }
    } else {
        // ---- KV path (compacted tokens) ----
        const int kvid = blockIdx.x - 512;
        const int bn0 = (kvid & 15) * 128;       // over N_KV
        const int yy  = kvid >> 4;
        const int bb  = yy >> 4;
        const int tile = yy & 15;
        const int nc = ncomp[bb];
        if (tile * 128 >= nc) return;

        int ci = tile * 128 + row;
        if (ci >= nc) ci = nc - 1;
        const int token = toklist[bb * TT + ci];
        const size_t a_off = (size_t)(bb * TT + token) * DD + kc;
        const size_t b_off = (size_t)(DD + bn0 + row) * DD + kc;  // W rows 1024+
        gemm_core(sb, A, W, a_off, b_off,
                  tid, wm, wn, a_r, a_k, b_r, b_k, acc);

        #pragma unroll
        for (int mi = 0; mi < 4; mi++) {
            const int rin = wm * 64 + mi * 16 + (lane >> 2);
            const int crow0 = tile * 128 + rin;
            const int crow1 = crow0 + 8;
            #pragma unroll
            for (int nf = 0; nf < 4; nf++) {
                const int col = bn0 + wn * 32 + nf * 8 + (lane & 3) * 2;
                const float b0 = bias[DD + col], b1 = bias[DD + col + 1];
                float v0 = acc[mi][nf][0] + b0, v1 = acc[mi][nf][1] + b1;
                float v2 = acc[mi][nf][2] + b0, v3 = acc[mi][nf][3] + b1;
                __half* G = (col < DD) ? k_g : v_g;
                const int hh = (col >> 6) & 15;
                const int d  = col & 63;
                const size_t hb = ((size_t)(bb * 16 + hh)) * TT;
                if (crow0 < nc)
                    *(uint32_t*)(G + (hb + crow0) * 64 + d) = pack2h(v0, v1);
                if (crow1 < nc)
                    *(uint32_t*)(G + (hb + crow1) * 64 + d) = pack2h(v2, v3);
            }
        }
    }
}

// ---------------------------------------------------------------------------
// Out-projection GEMM (dense, plain epilogue).
// ---------------------------------------------------------------------------
__global__ __launch_bounds__(256, 2)
void gemm_tc_kernel(const __half* __restrict__ A,
                    const __half* __restrict__ B,
                    const float* __restrict__ bias, float* __restrict__ C)
{
    extern __shared__ char smraw[];
    const uint32_t sb = smem_u32(smraw);
    const int tid = threadIdx.x, wid = tid >> 5, lane = tid & 31;
    const int bm0 = blockIdx.y * 128, bn0 = blockIdx.x * 128;
    const int wm = wid >> 2, wn = wid & 3;
    const int a_r = (lane & 7) + ((lane >> 3) & 1) * 8;
    const int a_k = (lane >> 4) * 8;
    const int b_r = (lane & 7) + (lane >> 4) * 8;
    const int b_k = ((lane >> 3) & 1) * 8;
    const int row = tid >> 1, kc = (tid & 1) * 32;
    const size_t a_off = (size_t)(bm0 + row) * DD + kc;
    const size_t b_off = (size_t)(bn0 + row) * DD + kc;

    float acc[4][4][4];
    #pragma unroll
    for (int i = 0; i < 4; i++)
        #pragma unroll
        for (int j = 0; j < 4; j++)
            #pragma unroll
            for (int v = 0; v < 4; v++) acc[i][j][v] = 0.0f;

    gemm_core(sb, A, B, a_off, b_off,
              tid, wm, wn, a_r, a_k, b_r, b_k, acc);

    #pragma unroll
    for (int mi = 0; mi < 4; mi++) {
        const int orow = bm0 + wm * 64 + mi * 16 + (lane >> 2);
        #pragma unroll
        for (int nf = 0; nf < 4; nf++) {
            const int col = bn0 + wn * 32 + nf * 8 + (lane & 3) * 2;
            const float b0 = bias[col], b1 = bias[col + 1];
            float2 p0, p1;
            p0.x = acc[mi][nf][0] + b0; p0.y = acc[mi][nf][1] + b1;
            p1.x = acc[mi][nf][2] + b0; p1.y = acc[mi][nf][3] + b1;
            *(float2*)&C[(size_t)orow * DD + col]       = p0;
            *(float2*)&C[(size_t)(orow + 8) * DD + col] = p1;
        }
    }
}

// ---------------------------------------------------------------------------
// Tensor-core flash attention over COMPACTED K/V. All operands single fp16.
// Full tiles skip validity selects; only the tail tile masks.
// ---------------------------------------------------------------------------
#define AVROW 72                       // half row stride (144 B)
#define KQ  0                          // Q: 128*144 = 18432 (region 0)
#define KK  0
#define KV  9216
#define ASTAGE 18432
#define ATTN_SMEM (2 * ASTAGE + 256)   // 37120

__device__ __forceinline__ void attn_kvload(
    uint32_t sb, int region, int bh, int n0,
    const __half* __restrict__ K_g, const __half* __restrict__ V_g, int tid)
{
    const uint32_t st = sb + (uint32_t)region * ASTAGE;
    const size_t gb = ((size_t)bh * TT + n0) * 64;
    #pragma unroll
    for (int u = 0; u < 2; u++) {
        int idx = tid * 2 + u;
        int row = idx >> 3, ch = idx & 7;
        uint32_t so = (uint32_t)(row * 144 + ch * 16);
        size_t go = gb + row * 64 + ch * 8;
        cpa16(st + KK + so, K_g + go);
        cpa16(st + KV + so, V_g + go);
    }
}

__global__ __launch_bounds__(256, 2)
void attn_tc_kernel(const __half* __restrict__ Q_g,
                    const __half* __restrict__ K_g,
                    const __half* __restrict__ V_g,
                    const int* __restrict__ ncomp,
                    __half* __restrict__ O_g)
{
    extern __shared__ char smraw[];
    const uint32_t sb = smem_u32(smraw);
    const int tid = threadIdx.x, wid = tid >> 5, lane = tid & 31;
    const int bh = blockIdx.y;
    const int b = bh >> 4, h = bh & 15;
    const int t0 = blockIdx.x * 128;
    const int wm = wid;

    const int a_r = (lane & 7) + ((lane >> 3) & 1) * 8;
    const int a_k = (lane >> 4) * 8;
    const int b_r = (lane & 7) + (lane >> 4) * 8;
    const int b_k = ((lane >> 3) & 1) * 8;
    const int c0base = (lane & 3) * 2;

    const int nc = ncomp[b];
    const int ntiles = (nc + 63) >> 6;

    // Q -> region 0; KV tile 0 -> region 1
    const size_t qbase = ((size_t)bh * TT + t0) * 64;
    #pragma unroll
    for (int i = 0; i < 4; i++) {
        int f = tid + i * 256;
        int row = f >> 3, ch = f & 7;
        uint32_t so = (uint32_t)(row * 144 + ch * 16);
        cpa16(sb + KQ + so, Q_g + qbase + row * 64 + ch * 8);
    }
    attn_kvload(sb, 1, bh, 0, K_g, V_g, tid);
    CP_COMMIT();
    CP_WAIT(0);
    __syncthreads();

    uint32_t qf[4][4];
    #pragma unroll
    for (int kk = 0; kk < 4; kk++) {
        uint32_t addr = (uint32_t)(((wm * 16 + a_r) * AVROW + kk * 16 + a_k) * 2);
        ldsm4(qf[kk], sb + KQ + addr);
    }
    __syncthreads();

    float O[8][4];
    #pragma unroll
    for (int j = 0; j < 8; j++)
        #pragma unroll
        for (int v = 0; v < 4; v++) O[j][v] = 0.0f;
    float m0 = -3.0e38f, m1 = -3.0e38f, l0 = 0.0f, l1 = 0.0f;

    for (int t = 0; t < ntiles; t++) {
        const int rt = (t + 1) & 1;
        if (t + 1 < ntiles) {
            attn_kvload(sb, t & 1, bh, (t + 1) * 64, K_g, V_g, tid);
            CP_COMMIT();
        }
        const uint32_t st = sb + (uint32_t)rt * ASTAGE;
        const int kbase = t * 64;

        float acc[8][4];
        #pragma unroll
        for (int j = 0; j < 8; j++)
            #pragma unroll
            for (int v = 0; v < 4; v++) acc[j][v] = 0.0f;

        #pragma unroll
        for (int kk = 0; kk < 4; kk++) {
            #pragma unroll
            for (int nb = 0; nb < 4; nb++) {
                uint32_t addr = (uint32_t)(((nb * 16 + b_r) * AVROW
                                            + kk * 16 + b_k) * 2);
                uint32_t rk[4];
                ldsm4(rk, st + KK + addr);
                mma_f16(acc[2 * nb],     qf[kk], &rk[0]);
                mma_f16(acc[2 * nb + 1], qf[kk], &rk[2]);
            }
        }

        float rmax0 = -3.0e38f, rmax1 = -3.0e38f;
        if (kbase + 64 <= nc) {
            #pragma unroll
            for (int j = 0; j < 8; j++) {
                rmax0 = fmaxf(rmax0, fmaxf(acc[j][0], acc[j][1]));
                rmax1 = fmaxf(rmax1, fmaxf(acc[j][2], acc[j][3]));
            }
        } else {
            #pragma unroll
            for (int j = 0; j < 8; j++) {
                int c = kbase + j * 8 + c0base;
                bool v0 = (c < nc), v1 = (c + 1 < nc);
                acc[j][0] = v0 ? acc[j][0] : -1000.0f;
                acc[j][1] = v1 ? acc[j][1] : -1000.0f;
                acc[j][2] = v0 ? acc[j][2] : -1000.0f;
                acc[j][3] = v1 ? acc[j][3] : -1000.0f;
                rmax0 = fmaxf(rmax0, fmaxf(acc[j][0], acc[j][1]));
                rmax1 = fmaxf(rmax1, fmaxf(acc[j][2], acc[j][3]));
            }
        }
        rmax0 = fmaxf(rmax0, __shfl_xor_sync(0xffffffffu, rmax0, 1));
        rmax0 = fmaxf(rmax0, __shfl_xor_sync(0xffffffffu, rmax0, 2));
        rmax1 = fmaxf(rmax1, __shfl_xor_sync(0xffffffffu, rmax1, 1));
        rmax1 = fmaxf(rmax1, __shfl_xor_sync(0xffffffffu, rmax1, 2));

        float mn0 = fmaxf(m0, rmax0), mn1 = fmaxf(m1, rmax1);
        float al0 = __expf(m0 - mn0), al1 = __expf(m1 - mn1);
        m0 = mn0; m1 = mn1;

        float rs0 = 0.0f, rs1 = 0.0f;
        #pragma unroll
        for (int j = 0; j < 8; j++) {
            acc[j][0] = __expf(acc[j][0] - mn0); rs0 += acc[j][0];
            acc[j][1] = __expf(acc[j][1] - mn0); rs0 += acc[j][1];
            acc[j][2] = __expf(acc[j][2] - mn1); rs1 += acc[j][2];
            acc[j][3] = __expf(acc[j][3] - mn1); rs1 += acc[j][3];
        }
        rs0 += __shfl_xor_sync(0xffffffffu, rs0, 1);
        rs0 += __shfl_xor_sync(0xffffffffu, rs0, 2);
        rs1 += __shfl_xor_sync(0xffffffffu, rs1, 1);
        rs1 += __shfl_xor_sync(0xffffffffu, rs1, 2);
        l0 = l0 * al0 + rs0;
        l1 = l1 * al1 + rs1;
        #pragma unroll
        for (int j = 0; j < 8; j++) {
            O[j][0] *= al0; O[j][1] *= al0;
            O[j][2] *= al1; O[j][3] *= al1;
        }

        #pragma unroll
        for (int kk = 0; kk < 4; kk++) {
            uint32_t pa[4];
            pa[0] = pack2h(acc[2 * kk][0],     acc[2 * kk][1]);
            pa[1] = pack2h(acc[2 * kk][2],     acc[2 * kk][3]);
            pa[2] = pack2h(acc[2 * kk + 1][0], acc[2 * kk + 1][1]);
            pa[3] = pack2h(acc[2 * kk + 1][2], acc[2 * kk + 1][3]);
            #pragma unroll
            for (int nb = 0; nb < 4; nb++) {
                uint32_t addr = (uint32_t)(((kk * 16 + ((lane >> 3) & 1) * 8
                                             + (lane & 7)) * AVROW
                                            + nb * 16 + (lane >> 4) * 8) * 2);
                uint32_t v4[4];
                ldsm4t(v4, st + KV + addr);
                mma_f16(O[2 * nb],     pa, &v4[0]);
                mma_f16(O[2 * nb + 1], pa, &v4[2]);
            }
        }

        if (t + 1 < ntiles) CP_WAIT(0);
        __syncthreads();
    }

    const float inv0 = 1.0f / l0, inv1 = 1.0f / l1;
    const int trow = t0 + wm * 16 + (lane >> 2);
    const size_t ob0 = ((size_t)(b * TT + trow)) * DD + h * 64;
    const size_t ob1 = ob0 + (size_t)8 * DD;
    #pragma unroll
    for (int jn = 0; jn < 8; jn++) {
        int c = jn * 8 + c0base;
        *(uint32_t*)(O_g + ob0 + c) = pack2h(O[jn][0] * inv0, O[jn][1] * inv0);
        *(uint32_t*)(O_g + ob1 + c) = pack2h(O[jn][2] * inv1, O[jn][3] * inv1);
    }
}

// ---------------------------------------------------------------------------
extern "C" void kernel_launch(void* const* d_in, const int* in_sizes, int n_in,
                              void* d_out, int out_size)
{
    const float* x     = (const float*)d_in[0];
    const int*   mask  = (const int*)  d_in[1];
    const float* W_qkv = (const float*)d_in[2];
    const float* b_qkv = (const float*)d_in[3];
    const float* W_out = (const float*)d_in[4];
    const float* b_out = (const float*)d_in[5];
    float* out = (float*)d_out;

    __half *wq, *wo, *xs, *qg, *kg, *vg;
    int *toklist, *ncomp;
    cudaGetSymbolAddress((void**)&wq, g_wqkv);
    cudaGetSymbolAddress((void**)&wo, g_wout);
    cudaGetSymbolAddress((void**)&xs, g_act);
    cudaGetSymbolAddress((void**)&qg, g_q);
    cudaGetSymbolAddress((void**)&kg, g_k);
    cudaGetSymbolAddress((void**)&vg, g_v);
    cudaGetSymbolAddress((void**)&toklist, g_toklist);
    cudaGetSymbolAddress((void**)&ncomp,   g_ncomp);

    cudaFuncSetAttribute(gemm_proj_kernel,
                         cudaFuncAttributeMaxDynamicSharedMemorySize, GEMM_SMEM);
    cudaFuncSetAttribute(gemm_tc_kernel,
                         cudaFuncAttributeMaxDynamicSharedMemorySize, GEMM_SMEM);
    cudaFuncSetAttribute(attn_tc_kernel,
                         cudaFuncAttributeMaxDynamicSharedMemorySize, ATTN_SMEM);

    // 0) Fused fp16 conversion + mask scan
    conv_all_kernel<<<8196, 256>>>(W_qkv, W_out, x, mask,
                                   wq, wo, xs, toklist, ncomp);

    // 1) Fused Q + K/V projection
    gemm_proj_kernel<<<1536, 256, GEMM_SMEM>>>(
        xs, wq, b_qkv, qg, kg, vg, toklist, ncomp);

    // 2) Flash attention over compacted K/V (writes O fp16 -> xs)
    attn_tc_kernel<<<dim3(TT / 128, BB * HH), 256, ATTN_SMEM>>>(
        qg, kg, vg, ncomp, xs);

    // 3) Output projection
    gemm_tc_kernel<<<dim3(DD / 128, MTOT / 128), 256, GEMM_SMEM>>>(
        xs, wo, b_out, out);
}

// round 17
// speedup vs baseline: 1.0863x; 1.0863x over previous
#include <cuda_runtime.h>
#include <cuda_fp16.h>
#include <cstdint>
#include <math.h>

// Problem constants
#define BB 4
#define TT 2048
#define DD 1024
#define HH 16
#define DH 64
#define MTOT (BB*TT)        // 8192
#define N_QKV (3*DD)        // 3072
#define N_KV  (2*DD)        // 2048

// Scratch (device globals: allocation-guard safe). ALL single fp16.
__device__ __half g_wqkv[(size_t)N_QKV * DD];    // W_qkv^T [3072,1024]
__device__ __half g_wout[(size_t)DD * DD];       // W_out^T
__device__ __half g_act[(size_t)MTOT * DD];      // activations [M,K]
#define QKV_ELEMS ((size_t)BB * HH * TT * DH)
__device__ __half g_q[QKV_ELEMS];                // Q (pre-scaled 1/8)
__device__ __half g_k[QKV_ELEMS];                // K (compacted)
__device__ __half g_v[QKV_ELEMS];                // V (compacted)
// mask compaction: counts and compacted-index -> token map
__device__ int g_toklist[BB * TT];
__device__ int g_ncomp[BB];

// ---------------------------------------------------------------------------
// sm_80-portable PTX helpers
// ---------------------------------------------------------------------------
__device__ __forceinline__ uint32_t smem_u32(const void* p) {
    uint32_t a;
    asm("{ .reg .u64 t; cvta.to.shared.u64 t, %1; cvt.u32.u64 %0, t; }"
        : "=r"(a) : "l"(p));
    return a;
}
__device__ __forceinline__ void cpa16(uint32_t dst, const void* src) {
    asm volatile("cp.async.cg.shared.global [%0], [%1], 16;"
                 :: "r"(dst), "l"(src));
}
#define CP_COMMIT() asm volatile("cp.async.commit_group;" ::: "memory")
#define CP_WAIT(n)  asm volatile("cp.async.wait_group %0;" :: "n"(n) : "memory")

__device__ __forceinline__ void ldsm4(uint32_t* r, uint32_t addr) {
    asm volatile("ldmatrix.sync.aligned.m8n8.x4.shared.b16 {%0,%1,%2,%3}, [%4];"
                 : "=r"(r[0]), "=r"(r[1]), "=r"(r[2]), "=r"(r[3]) : "r"(addr));
}
__device__ __forceinline__ void ldsm4t(uint32_t* r, uint32_t addr) {
    asm volatile("ldmatrix.sync.aligned.m8n8.x4.trans.shared.b16 {%0,%1,%2,%3}, [%4];"
                 : "=r"(r[0]), "=r"(r[1]), "=r"(r[2]), "=r"(r[3]) : "r"(addr));
}
__device__ __forceinline__ void mma_f16(float* d, const uint32_t* a,
                                        const uint32_t* b) {
    asm volatile("mma.sync.aligned.m16n8k16.row.col.f32.f16.f16.f32 "
                 "{%0,%1,%2,%3}, {%4,%5,%6,%7}, {%8,%9}, {%0,%1,%2,%3};"
                 : "+f"(d[0]), "+f"(d[1]), "+f"(d[2]), "+f"(d[3])
                 : "r"(a[0]), "r"(a[1]), "r"(a[2]), "r"(a[3]),
                   "r"(b[0]), "r"(b[1]));
}
__device__ __forceinline__ uint32_t pack2h(float x, float y) {
    __half2 h;
    h.x = __float2half(x);
    h.y = __float2half(y);
    return *(uint32_t*)&h;
}

// ---------------------------------------------------------------------------
// Fused conversion kernel: weights + activations to fp16, mask scan.
// ---------------------------------------------------------------------------
__device__ __forceinline__ void conv_w_body(
    const float* __restrict__ W, __half* __restrict__ Wt,
    int K, int N, int bx, int by, int tid)
{
    __shared__ float t[32][33];
    const int n0 = bx * 32, k0 = by * 32;
    const int tx = tid & 31, ty = tid >> 5;
    #pragma unroll
    for (int i = 0; i < 32; i += 8)
        t[ty + i][tx] = W[(size_t)(k0 + ty + i) * N + n0 + tx];
    __syncthreads();
    #pragma unroll
    for (int i = 0; i < 32; i += 8) {
        int n = ty + i;
        Wt[(size_t)(n0 + n) * K + k0 + tx] = __float2half(t[tx][n]);
    }
}

__global__ __launch_bounds__(256)
void conv_all_kernel(const float* __restrict__ W_qkv,
                     const float* __restrict__ W_out,
                     const float* __restrict__ x,
                     const int* __restrict__ mask,
                     __half* __restrict__ wq, __half* __restrict__ wo,
                     __half* __restrict__ xs,
                     int* __restrict__ toklist, int* __restrict__ ncomp)
{
    const int bid = blockIdx.x, tid = threadIdx.x;
    if (bid < 3072) {
        conv_w_body(W_qkv, wq, DD, N_QKV, bid % 96, bid / 96, tid);
    } else if (bid < 4096) {
        const int id = bid - 3072;
        conv_w_body(W_out, wo, DD, DD, id % 32, id / 32, tid);
    } else if (bid < 8192) {
        const int base = (bid - 4096) * 512 + tid;
        #pragma unroll
        for (int u = 0; u < 2; u++) {
            int idx = base + u * 256;
            float4 v = ((const float4*)x)[idx];
            ((uint32_t*)xs)[idx * 2 + 0] = pack2h(v.x, v.y);
            ((uint32_t*)xs)[idx * 2 + 1] = pack2h(v.z, v.w);
        }
    } else {
        const int bb = bid - 8192;
        const int* mrow = mask + bb * TT;
        __shared__ int part[256];
        int loc[8];
        int s = 0;
        const int base = tid * 8;
        #pragma unroll
        for (int i = 0; i < 8; i++) {
            loc[i] = s;
            s += (mrow[base + i] != 0) ? 1 : 0;
        }
        part[tid] = s;
        __syncthreads();
        for (int off = 1; off < 256; off <<= 1) {
            int v = (tid >= off) ? part[tid - off] : 0;
            __syncthreads();
            part[tid] += v;
            __syncthreads();
        }
        const int excl = (tid == 0) ? 0 : part[tid - 1];
        #pragma unroll
        for (int i = 0; i < 8; i++)
            if (mrow[base + i] != 0)
                toklist[bb * TT + excl + loc[i]] = base + i;
        if (tid == 255) ncomp[bb] = part[255];
    }
}

// ---------------------------------------------------------------------------
// GEMM machinery: single fp16 A and B. BK=32, 80B rows,
// 3-stage cp.async ring (chunk c in stage c%3, prefetch distance 2,
// ONE __syncthreads per chunk).
// ---------------------------------------------------------------------------
#define GBK 32
#define MATB (128 * 80)                // 10240 bytes per matrix tile
#define ST_A  0
#define ST_B  MATB
#define STAGE_B (2 * MATB)             // 20480
#define GEMM_SMEM (3 * STAGE_B)        // 61440

__device__ __forceinline__ void gemm_compute_chunk(
    uint32_t st, int wm, int wn,
    int a_r, int a_k, int b_r, int b_k,
    float acc[4][4][4])
{
    #pragma unroll
    for (int ks = 0; ks < 2; ks++) {
        const int k0 = ks * 16;
        uint32_t bf[4][2];
        #pragma unroll
        for (int half = 0; half < 2; half++) {
            uint32_t baddr = (uint32_t)((wn * 32 + half * 16 + b_r) * 80
                                        + (k0 + b_k) * 2);
            uint32_t r[4];
            ldsm4(r, st + ST_B + baddr);
            bf[half * 2 + 0][0] = r[0]; bf[half * 2 + 0][1] = r[1];
            bf[half * 2 + 1][0] = r[2]; bf[half * 2 + 1][1] = r[3];
        }
        #pragma unroll
        for (int mi = 0; mi < 4; mi++) {
            uint32_t aaddr = (uint32_t)((wm * 64 + mi * 16 + a_r) * 80
                                        + (k0 + a_k) * 2);
            uint32_t a4[4];
            ldsm4(a4, st + ST_A + aaddr);
            #pragma unroll
            for (int nf = 0; nf < 4; nf++) mma_f16(acc[mi][nf], a4, bf[nf]);
        }
    }
}

__device__ __forceinline__ void gemm_load_chunk_rows(
    uint32_t stBase,
    const __half* __restrict__ A, const __half* __restrict__ B,
    size_t a_row_off, size_t b_row_off, int k0, int tid)
{
    const int kc = (tid & 1) * 16;
    const int row = tid >> 1;
    const uint32_t so = (uint32_t)(row * 80 + kc * 2);
    cpa16(stBase + ST_A + so,      A + a_row_off + k0);
    cpa16(stBase + ST_A + so + 16, A + a_row_off + k0 + 8);
    cpa16(stBase + ST_B + so,      B + b_row_off + k0);
    cpa16(stBase + ST_B + so + 16, B + b_row_off + k0 + 8);
}

__device__ __forceinline__ void gemm_core(
    uint32_t sb,
    const __half* __restrict__ A, const __half* __restrict__ B,
    size_t a_off, size_t b_off, int tid, int wm, int wn,
    int a_r, int a_k, int b_r, int b_k, float acc[4][4][4])
{
    const int NCH = DD / GBK;   // 32
    // prologue: chunks 0,1 -> stages 0,1
    gemm_load_chunk_rows(sb + 0 * STAGE_B, A, B, a_off, b_off, 0, tid);
    CP_COMMIT();
    gemm_load_chunk_rows(sb + 1 * STAGE_B, A, B, a_off, b_off, GBK, tid);
    CP_COMMIT();

    int s_cur = 0;   // stage of chunk c      (= c % 3)
    int s_pre = 2;   // stage of chunk c + 2  (= (c+2) % 3)
    for (int c = 0; c < NCH; c++) {
        if (c + 1 < NCH) CP_WAIT(1); else CP_WAIT(0);   // chunk c arrived
        __syncthreads();   // all warps finished compute(c-1) -> stage s_pre free

        if (c + 2 < NCH) {
            gemm_load_chunk_rows(sb + (uint32_t)s_pre * STAGE_B,
                                 A, B, a_off, b_off, (c + 2) * GBK, tid);
            CP_COMMIT();
        }
        gemm_compute_chunk(sb + (uint32_t)s_cur * STAGE_B,
                           wm, wn, a_r, a_k, b_r, b_k, acc);

        s_cur = (s_cur == 2) ? 0 : s_cur + 1;
        s_pre = (s_pre == 2) ? 0 : s_pre + 1;
    }
}

// ---------------------------------------------------------------------------
// Fused projection kernel: blocks [0,512) = Q (dense, scatter pre-scaled);
// blocks [512,1536) = K/V over compacted tokens only.
// ---------------------------------------------------------------------------
__global__ __launch_bounds__(256, 2)
void gemm_proj_kernel(const __half* __restrict__ A,
                      const __half* __restrict__ W,
                      const float* __restrict__ bias,
                      __half* q_g, __half* k_g, __half* v_g,
                      const int* __restrict__ toklist,
                      const int* __restrict__ ncomp)
{
    extern __shared__ char smraw[];
    const uint32_t sb = smem_u32(smraw);
    const int tid = threadIdx.x, wid = tid >> 5, lane = tid & 31;
    const int wm = wid >> 2, wn = wid & 3;
    const int a_r = (lane & 7) + ((lane >> 3) & 1) * 8;
    const int a_k = (lane >> 4) * 8;
    const int b_r = (lane & 7) + (lane >> 4) * 8;
    const int b_k = ((lane >> 3) & 1) * 8;
    const int row = tid >> 1, kc = (tid & 1) * 16;

    float acc[4][4][4];
    #pragma unroll
    for (int i = 0; i < 4; i++)
        #pragma unroll
        for (int j = 0; j < 4; j++)
            #pragma unroll
            for (int v = 0; v < 4; v++) acc[i][j][v] = 0.0f;

    if (blockIdx.x < 512) {
        // ---- Q path ----
        const int qid = blockIdx.x;
        const int bn0 = (qid & 7) * 128;
        const int bm0 = (qid >> 3) * 128;
        const size_t a_off = (size_t)(bm0 + row) * DD + kc;
        const size_t b_off = (size_t)(bn0 + row) * DD + kc;
        gemm_core(sb, A, W, a_off, b_off,
                  tid, wm, wn, a_r, a_k, b_r, b_k, acc);

        #pragma unroll
        for (int mi = 0; mi < 4; mi++) {
            const int orow = bm0 + wm * 64 + mi * 16 + (lane >> 2);
            #pragma unroll
            for (int nf = 0; nf < 4; nf++) {
                const int col = bn0 + wn * 32 + nf * 8 + (lane & 3) * 2;
                const float b0 = bias[col], b1 = bias[col + 1];
                float v0 = acc[mi][nf][0] + b0, v1 = acc[mi][nf][1] + b1;
                float v2 = acc[mi][nf][2] + b0, v3 = acc[mi][nf][3] + b1;
                const int hh  = (col >> 6) & 15;
                const int d   = col & 63;
                const int bb  = orow >> 11;
                const int trow = orow & 2047;
                size_t dst = (((size_t)(bb * 16 + hh)) * TT + trow) * 64 + d;
                *(uint32_t*)(q_g + dst) = pack2h(v0 * 0.125f, v1 * 0.125f);
                *(uint32_t*)(q_g + dst + 8 * 64) = pack2h(v2 * 0.125f, v3 * 0.125f);
            }
        }
    } else {
        // ---- KV path (compacted tokens) ----
        const int kvid = blockIdx.x - 512;
        const int bn0 = (kvid & 15) * 128;       // over N_KV
        const int yy  = kvid >> 4;
        const int bb  = yy >> 4;
        const int tile = yy & 15;
        const int nc = ncomp[bb];
        if (tile * 128 >= nc) return;

        int ci = tile * 128 + row;
        if (ci >= nc) ci = nc - 1;
        const int token = toklist[bb * TT + ci];
        const size_t a_off = (size_t)(bb * TT + token) * DD + kc;
        const size_t b_off = (size_t)(DD + bn0 + row) * DD + kc;  // W rows 1024+
        gemm_core(sb, A, W, a_off, b_off,
                  tid, wm, wn, a_r, a_k, b_r, b_k, acc);

        #pragma unroll
        for (int mi = 0; mi < 4; mi++) {
            const int rin = wm * 64 + mi * 16 + (lane >> 2);
            const int crow0 = tile * 128 + rin;
            const int crow1 = crow0 + 8;
            #pragma unroll
            for (int nf = 0; nf < 4; nf++) {
                const int col = bn0 + wn * 32 + nf * 8 + (lane & 3) * 2;
                const float b0 = bias[DD + col], b1 = bias[DD + col + 1];
                float v0 = acc[mi][nf][0] + b0, v1 = acc[mi][nf][1] + b1;
                float v2 = acc[mi][nf][2] + b0, v3 = acc[mi][nf][3] + b1;
                __half* G = (col < DD) ? k_g : v_g;
                const int hh = (col >> 6) & 15;
                const int d  = col & 63;
                const size_t hb = ((size_t)(bb * 16 + hh)) * TT;
                if (crow0 < nc)
                    *(uint32_t*)(G + (hb + crow0) * 64 + d) = pack2h(v0, v1);
                if (crow1 < nc)
                    *(uint32_t*)(G + (hb + crow1) * 64 + d) = pack2h(v2, v3);
            }
        }
    }
}

// ---------------------------------------------------------------------------
// Out-projection GEMM (dense, plain epilogue).
// ---------------------------------------------------------------------------
__global__ __launch_bounds__(256, 2)
void gemm_tc_kernel(const __half* __restrict__ A,
                    const __half* __restrict__ B,
                    const float* __restrict__ bias, float* __restrict__ C)
{
    extern __shared__ char smraw[];
    const uint32_t sb = smem_u32(smraw);
    const int tid = threadIdx.x, wid = tid >> 5, lane = tid & 31;
    const int bm0 = blockIdx.y * 128, bn0 = blockIdx.x * 128;
    const int wm = wid >> 2, wn = wid & 3;
    const int a_r = (lane & 7) + ((lane >> 3) & 1) * 8;
    const int a_k = (lane >> 4) * 8;
    const int b_r = (lane & 7) + (lane >> 4) * 8;
    const int b_k = ((lane >> 3) & 1) * 8;
    const int row = tid >> 1, kc = (tid & 1) * 16;
    const size_t a_off = (size_t)(bm0 + row) * DD + kc;
    const size_t b_off = (size_t)(bn0 + row) * DD + kc;

    float acc[4][4][4];
    #pragma unroll
    for (int i = 0; i < 4; i++)
        #pragma unroll
        for (int j = 0; j < 4; j++)
            #pragma unroll
            for (int v = 0; v < 4; v++) acc[i][j][v] = 0.0f;

    gemm_core(sb, A, B, a_off, b_off,
              tid, wm, wn, a_r, a_k, b_r, b_k, acc);

    #pragma unroll
    for (int mi = 0; mi < 4; mi++) {
        const int orow = bm0 + wm * 64 + mi * 16 + (lane >> 2);
        #pragma unroll
        for (int nf = 0; nf < 4; nf++) {
            const int col = bn0 + wn * 32 + nf * 8 + (lane & 3) * 2;
            const float b0 = bias[col], b1 = bias[col + 1];
            float2 p0, p1;
            p0.x = acc[mi][nf][0] + b0; p0.y = acc[mi][nf][1] + b1;
            p1.x = acc[mi][nf][2] + b0; p1.y = acc[mi][nf][3] + b1;
            *(float2*)&C[(size_t)orow * DD + col]       = p0;
            *(float2*)&C[(size_t)(orow + 8) * DD + col] = p1;
        }
    }
}

// ---------------------------------------------------------------------------
// Tensor-core flash attention over COMPACTED K/V. All operands single fp16.
// Full tiles skip validity selects; only the tail tile masks.
// ---------------------------------------------------------------------------
#define AVROW 72                       // half row stride (144 B)
#define KQ  0                          // Q: 128*144 = 18432 (region 0)
#define KK  0
#define KV  9216
#define ASTAGE 18432
#define ATTN_SMEM (2 * ASTAGE + 256)   // 37120

__device__ __forceinline__ void attn_kvload(
    uint32_t sb, int region, int bh, int n0,
    const __half* __restrict__ K_g, const __half* __restrict__ V_g, int tid)
{
    const uint32_t st = sb + (uint32_t)region * ASTAGE;
    const size_t gb = ((size_t)bh * TT + n0) * 64;
    #pragma unroll
    for (int u = 0; u < 2; u++) {
        int idx = tid * 2 + u;
        int row = idx >> 3, ch = idx & 7;
        uint32_t so = (uint32_t)(row * 144 + ch * 16);
        size_t go = gb + row * 64 + ch * 8;
        cpa16(st + KK + so, K_g + go);
        cpa16(st + KV + so, V_g + go);
    }
}

__global__ __launch_bounds__(256, 2)
void attn_tc_kernel(const __half* __restrict__ Q_g,
                    const __half* __restrict__ K_g,
                    const __half* __restrict__ V_g,
                    const int* __restrict__ ncomp,
                    __half* __restrict__ O_g)
{
    extern __shared__ char smraw[];
    const uint32_t sb = smem_u32(smraw);
    const int tid = threadIdx.x, wid = tid >> 5, lane = tid & 31;
    const int bh = blockIdx.y;
    const int b = bh >> 4, h = bh & 15;
    const int t0 = blockIdx.x * 128;
    const int wm = wid;

    const int a_r = (lane & 7) + ((lane >> 3) & 1) * 8;
    const int a_k = (lane >> 4) * 8;
    const int b_r = (lane & 7) + (lane >> 4) * 8;
    const int b_k = ((lane >> 3) & 1) * 8;
    const int c0base = (lane & 3) * 2;

    const int nc = ncomp[b];
    const int ntiles = (nc + 63) >> 6;

    // Q -> region 0; KV tile 0 -> region 1
    const size_t qbase = ((size_t)bh * TT + t0) * 64;
    #pragma unroll
    for (int i = 0; i < 4; i++) {
        int f = tid + i * 256;
        int row = f >> 3, ch = f & 7;
        uint32_t so = (uint32_t)(row * 144 + ch * 16);
        cpa16(sb + KQ + so, Q_g + qbase + row * 64 + ch * 8);
    }
    attn_kvload(sb, 1, bh, 0, K_g, V_g, tid);
    CP_COMMIT();
    CP_WAIT(0);
    __syncthreads();

    uint32_t qf[4][4];
    #pragma unroll
    for (int kk = 0; kk < 4; kk++) {
        uint32_t addr = (uint32_t)(((wm * 16 + a_r) * AVROW + kk * 16 + a_k) * 2);
        ldsm4(qf[kk], sb + KQ + addr);
    }
    __syncthreads();

    float O[8][4];
    #pragma unroll
    for (int j = 0; j < 8; j++)
        #pragma unroll
        for (int v = 0; v < 4; v++) O[j][v] = 0.0f;
    float m0 = -3.0e38f, m1 = -3.0e38f, l0 = 0.0f, l1 = 0.0f;

    for (int t = 0; t < ntiles; t++) {
        const int rt = (t + 1) & 1;
        if (t + 1 < ntiles) {
            attn_kvload(sb, t & 1, bh, (t + 1) * 64, K_g, V_g, tid);
            CP_COMMIT();
        }
        const uint32_t st = sb + (uint32_t)rt * ASTAGE;
        const int kbase = t * 64;

        float acc[8][4];
        #pragma unroll
        for (int j = 0; j < 8; j++)
            #pragma unroll
            for (int v = 0; v < 4; v++) acc[j][v] = 0.0f;

        #pragma unroll
        for (int kk = 0; kk < 4; kk++) {
            #pragma unroll
            for (int nb = 0; nb < 4; nb++) {
                uint32_t addr = (uint32_t)(((nb * 16 + b_r) * AVROW
                                            + kk * 16 + b_k) * 2);
                uint32_t rk[4];
                ldsm4(rk, st + KK + addr);
                mma_f16(acc[2 * nb],     qf[kk], &rk[0]);
                mma_f16(acc[2 * nb + 1], qf[kk], &rk[2]);
            }
        }

        float rmax0 = -3.0e38f, rmax1 = -3.0e38f;
        if (kbase + 64 <= nc) {
            #pragma unroll
            for (int j = 0; j < 8; j++) {
                rmax0 = fmaxf(rmax0, fmaxf(acc[j][0], acc[j][1]));
                rmax1 = fmaxf(rmax1, fmaxf(acc[j][2], acc[j][3]));
            }
        } else {
            #pragma unroll
            for (int j = 0; j < 8; j++) {
                int c = kbase + j * 8 + c0base;
                bool v0 = (c < nc), v1 = (c + 1 < nc);
                acc[j][0] = v0 ? acc[j][0] : -1000.0f;
                acc[j][1] = v1 ? acc[j][1] : -1000.0f;
                acc[j][2] = v0 ? acc[j][2] : -1000.0f;
                acc[j][3] = v1 ? acc[j][3] : -1000.0f;
                rmax0 = fmaxf(rmax0, fmaxf(acc[j][0], acc[j][1]));
                rmax1 = fmaxf(rmax1, fmaxf(acc[j][2], acc[j][3]));
            }
        }
        rmax0 = fmaxf(rmax0, __shfl_xor_sync(0xffffffffu, rmax0, 1));
        rmax0 = fmaxf(rmax0, __shfl_xor_sync(0xffffffffu, rmax0, 2));
        rmax1 = fmaxf(rmax1, __shfl_xor_sync(0xffffffffu, rmax1, 1));
        rmax1 = fmaxf(rmax1, __shfl_xor_sync(0xffffffffu, rmax1, 2));

        float mn0 = fmaxf(m0, rmax0), mn1 = fmaxf(m1, rmax1);
        float al0 = __expf(m0 - mn0), al1 = __expf(m1 - mn1);
        m0 = mn0; m1 = mn1;

        float rs0 = 0.0f, rs1 = 0.0f;
        #pragma unroll
        for (int j = 0; j < 8; j++) {
            acc[j][0] = __expf(acc[j][0] - mn0); rs0 += acc[j][0];
            acc[j][1] = __expf(acc[j][1] - mn0); rs0 += acc[j][1];
            acc[j][2] = __expf(acc[j][2] - mn1); rs1 += acc[j][2];
            acc[j][3] = __expf(acc[j][3] - mn1); rs1 += acc[j][3];
        }
        rs0 += __shfl_xor_sync(0xffffffffu, rs0, 1);
        rs0 += __shfl_xor_sync(0xffffffffu, rs0, 2);
        rs1 += __shfl_xor_sync(0xffffffffu, rs1, 1);
        rs1 += __shfl_xor_sync(0xffffffffu, rs1, 2);
        l0 = l0 * al0 + rs0;
        l1 = l1 * al1 + rs1;
        #pragma unroll
        for (int j = 0; j < 8; j++) {
            O[j][0] *= al0; O[j][1] *= al0;
            O[j][2] *= al1; O[j][3] *= al1;
        }

        #pragma unroll
        for (int kk = 0; kk < 4; kk++) {
            uint32_t pa[4];
            pa[0] = pack2h(acc[2 * kk][0],     acc[2 * kk][1]);
            pa[1] = pack2h(acc[2 * kk][2],     acc[2 * kk][3]);
            pa[2] = pack2h(acc[2 * kk + 1][0], acc[2 * kk + 1][1]);
            pa[3] = pack2h(acc[2 * kk + 1][2], acc[2 * kk + 1][3]);
            #pragma unroll
            for (int nb = 0; nb < 4; nb++) {
                uint32_t addr = (uint32_t)(((kk * 16 + ((lane >> 3) & 1) * 8
                                             + (lane & 7)) * AVROW
                                            + nb * 16 + (lane >> 4) * 8) * 2);
                uint32_t v4[4];
                ldsm4t(v4, st + KV + addr);
                mma_f16(O[2 * nb],     pa, &v4[0]);
                mma_f16(O[2 * nb + 1], pa, &v4[2]);
            }
        }

        if (t + 1 < ntiles) CP_WAIT(0);
        __syncthreads();
    }

    const float inv0 = 1.0f / l0, inv1 = 1.0f / l1;
    const int trow = t0 + wm * 16 + (lane >> 2);
    const size_t ob0 = ((size_t)(b * TT + trow)) * DD + h * 64;
    const size_t ob1 = ob0 + (size_t)8 * DD;
    #pragma unroll
    for (int jn = 0; jn < 8; jn++) {
        int c = jn * 8 + c0base;
        *(uint32_t*)(O_g + ob0 + c) = pack2h(O[jn][0] * inv0, O[jn][1] * inv0);
        *(uint32_t*)(O_g + ob1 + c) = pack2h(O[jn][2] * inv1, O[jn][3] * inv1);
    }
}

// ---------------------------------------------------------------------------
extern "C" void kernel_launch(void* const* d_in, const int* in_sizes, int n_in,
                              void* d_out, int out_size)
{
    const float* x     = (const float*)d_in[0];
    const int*   mask  = (const int*)  d_in[1];
    const float* W_qkv = (const float*)d_in[2];
    const float* b_qkv = (const float*)d_in[3];
    const float* W_out = (const float*)d_in[4];
    const float* b_out = (const float*)d_in[5];
    float* out = (float*)d_out;

    __half *wq, *wo, *xs, *qg, *kg, *vg;
    int *toklist, *ncomp;
    cudaGetSymbolAddress((void**)&wq, g_wqkv);
    cudaGetSymbolAddress((void**)&wo, g_wout);
    cudaGetSymbolAddress((void**)&xs, g_act);
    cudaGetSymbolAddress((void**)&qg, g_q);
    cudaGetSymbolAddress((void**)&kg, g_k);
    cudaGetSymbolAddress((void**)&vg, g_v);
    cudaGetSymbolAddress((void**)&toklist, g_toklist);
    cudaGetSymbolAddress((void**)&ncomp,   g_ncomp);

    cudaFuncSetAttribute(gemm_proj_kernel,
                         cudaFuncAttributeMaxDynamicSharedMemorySize, GEMM_SMEM);
    cudaFuncSetAttribute(gemm_tc_kernel,
                         cudaFuncAttributeMaxDynamicSharedMemorySize, GEMM_SMEM);
    cudaFuncSetAttribute(attn_tc_kernel,
                         cudaFuncAttributeMaxDynamicSharedMemorySize, ATTN_SMEM);

    // 0) Fused fp16 conversion + mask scan
    conv_all_kernel<<<8196, 256>>>(W_qkv, W_out, x, mask,
                                   wq, wo, xs, toklist, ncomp);

    // 1) Fused Q + K/V projection
    gemm_proj_kernel<<<1536, 256, GEMM_SMEM>>>(
        xs, wq, b_qkv, qg, kg, vg, toklist, ncomp);

    // 2) Flash attention over compacted K/V (writes O fp16 -> xs)
    attn_tc_kernel<<<dim3(TT / 128, BB * HH), 256, ATTN_SMEM>>>(
        qg, kg, vg, ncomp, xs);

    // 3) Output projection
    gemm_tc_kernel<<<dim3(DD / 128, MTOT / 128), 256, GEMM_SMEM>>>(
        xs, wo, b_out, out);
}